// round 14
// baseline (speedup 1.0000x reference)
#include <cuda_runtime.h>
#include <cuda_bf16.h>

// Problem constants
#define BB 64
#define LL 550
#define DD 768
#define RR 3
#define PP 50
#define LEN_KEEP (LL - RR * PP)   // 400
#define D4 (DD / 4)               // 192 float4 per feature row
#define TOTAL_F4 (BB * LEN_KEEP * D4)   // 4,915,200

#define THREADS 256
#define GRID 888                  // 148 SMs * 6 CTAs @ ~40 regs -> one wave
#define GSTRIDE (GRID * THREADS)  // 227,328

// Rank duty: 576 low-bid CTAs, 9 per batch, 62 positions each,
// j-loop split across the 8 warps (69-element chunks). (R12-proven.)
#define RANKERS 576
#define R_PER_B 9
#define SLICE_POS 62
#define JCHUNK 69

// Scratch + handshake (self-resetting -> graph-replay safe).
__device__ int g_src[BB * LEN_KEEP];  // float4 base addr of source row per rank
__device__ volatile int g_flag[BB];   // rank CTAs done per batch (-> 9)
__device__ int g_fin;                 // CTA completion counter (-> GRID)

__global__ __launch_bounds__(THREADS)
void fused_kernel(const float4* __restrict__ x,
                  const float*  __restrict__ noise,
                  const int*    __restrict__ indexes,
                  float*        __restrict__ out,
                  float4*       __restrict__ out4)
{
    __shared__ unsigned int sh_bits[LL];
    __shared__ int s_part[8 * 64];

    const int tid  = threadIdx.x;
    const int bid  = blockIdx.x;
    const int warp = tid >> 5;
    const int lane = tid & 31;

    // ======================= phase 1: rank duty =========================
    if (bid < RANKERS) {
        const int b     = bid / R_PER_B;
        const int slice = bid - b * R_PER_B;

        const int i0 = indexes[b * RR + 0];
        const int i1 = indexes[b * RR + 1];
        const int i2 = indexes[b * RR + 2];

        for (int j = tid; j < LL; j += THREADS) {
            const int blk = j / PP;
            float v = (blk == i0 || blk == i1 || blk == i2) ? 2.0f
                                                            : noise[b * LL + j];
            sh_bits[j] = __float_as_uint(v);  // non-negative -> bits ~ value
        }
        __syncthreads();

        const int base  = slice * SLICE_POS;
        const int n_pos = min(SLICE_POS, LL - base);
        const int p0 = base + lane;
        const int p1 = base + 32 + lane;
        const unsigned k0 = (lane < n_pos)      ? sh_bits[p0] : 0u;
        const unsigned k1 = (32 + lane < n_pos) ? sh_bits[p1] : 0u;

        const int j0 = warp * JCHUNK;
        const int j1 = min(LL, j0 + JCHUNK);
        int c0 = 0, c1 = 0;
        #pragma unroll 4
        for (int j = j0; j < j1; j++) {
            const unsigned bj = sh_bits[j];   // warp-uniform broadcast
            c0 += (int)((bj < k0) || ((bj == k0) && (j < p0)));
            c1 += (int)((bj < k1) || ((bj == k1) && (j < p1)));
        }
        s_part[warp * 64 + lane]      = c0;
        s_part[warp * 64 + 32 + lane] = c1;
        __syncthreads();

        if (tid < n_pos) {
            const int p = base + tid;
            int rank = 0;
            #pragma unroll
            for (int w = 0; w < 8; w++) rank += s_part[w * 64 + tid];

            const int OFF_MASK = BB * LEN_KEEP * DD;
            const int OFF_IDS  = OFF_MASK + BB * LL;
            out[OFF_MASK + b * LL + p] = (rank >= LEN_KEEP) ? 1.0f : 0.0f;
            out[OFF_IDS  + b * LL + p] = (float)rank;
            if (rank < LEN_KEEP)
                g_src[b * LEN_KEEP + rank] = (b * LL + p) * D4;
        }

        __syncthreads();
        __threadfence();
        if (tid == 0) atomicAdd((int*)&g_flag[b], 1);
    }

    // ================ wait ONCE for all batches to publish ===============
    if (tid < BB) {
        while (g_flag[tid] < R_PER_B) __nanosleep(64);
        __threadfence();                          // acquire
    }
    __syncthreads();

    // ============ phase 2: barrier-free streaming gather (MLP=4) =========
    int i = bid * THREADS + tid;

    while (i + 3 * GSTRIDE < TOTAL_F4) {
        int idx[4], src[4];
        #pragma unroll
        for (int k = 0; k < 4; k++) {
            idx[k] = i + k * GSTRIDE;
            const int row = idx[k] / D4;          // global kept-row (b*400+r)
            src[k] = __ldg(&g_src[row]) + (idx[k] - row * D4);
        }
        float4 v[4];
        #pragma unroll
        for (int k = 0; k < 4; k++) v[k] = __ldcs(&x[src[k]]);
        #pragma unroll
        for (int k = 0; k < 4; k++) __stcs(&out4[idx[k]], v[k]);
        i += 4 * GSTRIDE;
    }
    while (i < TOTAL_F4) {
        const int row = i / D4;
        const int src = __ldg(&g_src[row]) + (i - row * D4);
        __stcs(&out4[i], __ldcs(&x[src]));
        i += GSTRIDE;
    }

    // ======================= replay-safe reset ==========================
    __syncthreads();
    if (tid == 0) {
        const int prev = atomicAdd(&g_fin, 1);
        if (prev == GRID - 1) {
            #pragma unroll
            for (int j = 0; j < BB; j++) g_flag[j] = 0;
            g_fin = 0;
        }
    }
}

// ---------------------------------------------------------------------------
extern "C" void kernel_launch(void* const* d_in, const int* in_sizes, int n_in,
                              void* d_out, int out_size)
{
    const float* x       = (const float*)d_in[0];  // (64, 550, 768) f32
    const float* noise   = (const float*)d_in[1];  // (64, 550) f32
    const int*   indexes = (const int*)  d_in[2];  // (64, 3) i32
    float* out = (float*)d_out;  // [x_masked | mask | ids_restore] as f32

    fused_kernel<<<GRID, THREADS>>>(
        (const float4*)x, noise, indexes, out, (float4*)out);
}

// round 15
// speedup vs baseline: 1.1086x; 1.1086x over previous
#include <cuda_runtime.h>
#include <cuda_bf16.h>

// Problem constants
#define BB 64
#define LL 550
#define DD 768
#define RR 3
#define PP 50
#define LEN_KEEP (LL - RR * PP)   // 400
#define D4 (DD / 4)               // 192 float4 per feature row
#define TOTAL_F4 (BB * LEN_KEEP * D4)   // 4,915,200

#define THREADS 256
#define GRID 1184                 // 148 SMs * 8 CTAs -> one resident wave
#define NWARPS (GRID * 8)         // 9472
#define NCHUNK (TOTAL_F4 / 32)    // 153,600 chunks of 32 float4
#define CH_PER_ROW (D4 / 32)      // 6

// Rank duty (R12-proven): 576 CTAs, 9/batch, 62 positions, j split over warps.
#define RANKERS 576
#define R_PER_B 9
#define SLICE_POS 62
#define JCHUNK 69

// Scratch + handshake (self-resetting -> graph-replay safe).
__device__ int g_src[BB * LEN_KEEP];  // float4 base of source row per kept-rank
__device__ volatile int g_flag[BB];   // rank CTAs done per batch (-> 9)
__device__ int g_fin;                 // CTA completion counter (-> GRID)

__global__ __launch_bounds__(THREADS, 8)
void fused_kernel(const float4* __restrict__ x,
                  const float*  __restrict__ noise,
                  const int*    __restrict__ indexes,
                  float*        __restrict__ out,
                  float4*       __restrict__ out4)
{
    __shared__ unsigned int sh_bits[LL];
    __shared__ int s_part[8 * 64];

    const int tid  = threadIdx.x;
    const int bid  = blockIdx.x;
    const int warp = tid >> 5;
    const int lane = tid & 31;

    // ======================= phase 1: rank duty =========================
    if (bid < RANKERS) {
        const int b     = bid / R_PER_B;
        const int slice = bid - b * R_PER_B;

        const int i0 = indexes[b * RR + 0];
        const int i1 = indexes[b * RR + 1];
        const int i2 = indexes[b * RR + 2];

        for (int j = tid; j < LL; j += THREADS) {
            const int blk = j / PP;
            float v = (blk == i0 || blk == i1 || blk == i2) ? 2.0f
                                                            : noise[b * LL + j];
            sh_bits[j] = __float_as_uint(v);  // non-negative -> bits ~ value
        }
        __syncthreads();

        const int base  = slice * SLICE_POS;
        const int n_pos = min(SLICE_POS, LL - base);
        const int p0 = base + lane;
        const int p1 = base + 32 + lane;
        const unsigned k0 = (lane < n_pos)      ? sh_bits[p0] : 0u;
        const unsigned k1 = (32 + lane < n_pos) ? sh_bits[p1] : 0u;

        const int j0 = warp * JCHUNK;
        const int j1 = min(LL, j0 + JCHUNK);
        int c0 = 0, c1 = 0;
        #pragma unroll 4
        for (int j = j0; j < j1; j++) {
            const unsigned bj = sh_bits[j];   // warp-uniform broadcast
            c0 += (int)((bj < k0) || ((bj == k0) && (j < p0)));
            c1 += (int)((bj < k1) || ((bj == k1) && (j < p1)));
        }
        s_part[warp * 64 + lane]      = c0;
        s_part[warp * 64 + 32 + lane] = c1;
        __syncthreads();

        if (tid < n_pos) {
            const int p = base + tid;
            int rank = 0;
            #pragma unroll
            for (int w = 0; w < 8; w++) rank += s_part[w * 64 + tid];

            const int OFF_MASK = BB * LEN_KEEP * DD;
            const int OFF_IDS  = OFF_MASK + BB * LL;
            out[OFF_MASK + b * LL + p] = (rank >= LEN_KEEP) ? 1.0f : 0.0f;
            out[OFF_IDS  + b * LL + p] = (float)rank;
            if (rank < LEN_KEEP)
                g_src[b * LEN_KEEP + rank] = (b * LL + p) * D4;
        }

        __syncthreads();
        __threadfence();
        if (tid == 0) atomicAdd((int*)&g_flag[b], 1);
    }

    // ================ wait ONCE for all batches to publish ===============
    if (tid < BB) {
        while (g_flag[tid] < R_PER_B) __nanosleep(64);
        __threadfence();                          // acquire
    }
    __syncthreads();

    // ========== phase 2: warp-tiled barrier-free gather (MLP=4) ==========
    // One chunk = 32 consecutive float4 of one kept row -> row is
    // warp-uniform -> g_src load is a broadcast LDG (L1-hot, 100KB table).
    // No shared memory, no barriers; 4 independent chunks in flight.
    const int wglob = (bid << 3) | warp;          // 0..9471

    int c = wglob;
    while (c + 3 * NWARPS < NCHUNK) {
        int src[4], dst[4];
        #pragma unroll
        for (int k = 0; k < 4; k++) {
            const int ch  = c + k * NWARPS;
            const int row = ch / CH_PER_ROW;              // kept-row id
            const int sub = ch - row * CH_PER_ROW;        // 0..5
            src[k] = __ldg(&g_src[row]) + (sub << 5) + lane;
            dst[k] = (ch << 5) + lane;
        }
        float4 v[4];
        #pragma unroll
        for (int k = 0; k < 4; k++) v[k] = __ldcs(&x[src[k]]);
        #pragma unroll
        for (int k = 0; k < 4; k++) __stcs(&out4[dst[k]], v[k]);
        c += 4 * NWARPS;
    }
    while (c < NCHUNK) {
        const int row = c / CH_PER_ROW;
        const int sub = c - row * CH_PER_ROW;
        const int src = __ldg(&g_src[row]) + (sub << 5) + lane;
        __stcs(&out4[(c << 5) + lane], __ldcs(&x[src]));
        c += NWARPS;
    }

    // ======================= replay-safe reset ==========================
    __syncthreads();
    if (tid == 0) {
        const int prev = atomicAdd(&g_fin, 1);
        if (prev == GRID - 1) {
            #pragma unroll
            for (int j = 0; j < BB; j++) g_flag[j] = 0;
            g_fin = 0;
        }
    }
}

// ---------------------------------------------------------------------------
extern "C" void kernel_launch(void* const* d_in, const int* in_sizes, int n_in,
                              void* d_out, int out_size)
{
    const float* x       = (const float*)d_in[0];  // (64, 550, 768) f32
    const float* noise   = (const float*)d_in[1];  // (64, 550) f32
    const int*   indexes = (const int*)  d_in[2];  // (64, 3) i32
    float* out = (float*)d_out;  // [x_masked | mask | ids_restore] as f32

    fused_kernel<<<GRID, THREADS>>>(
        (const float4*)x, noise, indexes, out, (float4*)out);
}